// round 13
// baseline (speedup 1.0000x reference)
#include <cuda_runtime.h>
#include <cuda_bf16.h>
#include <cstdint>

// Problem dims
#define BATCH 8192
#define SEQ   128
#define EDIM  300
#define K1    600
#define K1P   640     // padded to multiple of BK
#define H1D   2048
#define H2D   2048
#define CDIM  1221
#define PADTOK 1

typedef __nv_bfloat16 bf16;

// ---------------------------------------------------------------------------
// Scratch (__device__ globals; zero-init -> K-padding cols stay zero)
// ---------------------------------------------------------------------------
__device__ bf16 g_feat_hi[(size_t)BATCH * K1P];
__device__ bf16 g_feat_lo[(size_t)BATCH * K1P];
__device__ bf16 g_h1_hi[(size_t)BATCH * H1D];
__device__ bf16 g_h1_lo[(size_t)BATCH * H1D];
__device__ bf16 g_h2_hi[(size_t)BATCH * H2D];
__device__ bf16 g_h2_lo[(size_t)BATCH * H2D];
__device__ bf16 g_W1_hi[(size_t)H1D * K1P];
__device__ bf16 g_W1_lo[(size_t)H1D * K1P];
__device__ bf16 g_W2_hi[(size_t)H2D * H1D];
__device__ bf16 g_W2_lo[(size_t)H2D * H1D];
__device__ bf16 g_Wo_hi[(size_t)CDIM * H2D];
__device__ bf16 g_Wo_lo[(size_t)CDIM * H2D];

__device__ __forceinline__ void split2(float v, bf16* hi, bf16* lo) {
    bf16 h = __float2bfloat16(v);
    *hi = h;
    *lo = __float2bfloat16(v - __bfloat162float(h));
}

// ---------------------------------------------------------------------------
// cp.async helpers (Ampere+; valid on base sm_103 target)
// ---------------------------------------------------------------------------
__device__ __forceinline__ void cp_async16(uint32_t dst, const void* src, int sz) {
    asm volatile("cp.async.cg.shared.global [%0], [%1], 16, %2;"
                 :: "r"(dst), "l"(src), "r"(sz) : "memory");
}
#define CP_COMMIT() asm volatile("cp.async.commit_group;" ::: "memory")
#define CP_WAIT1()  asm volatile("cp.async.wait_group 1;" ::: "memory")
#define CP_WAIT0()  asm volatile("cp.async.wait_group 0;" ::: "memory")

__device__ __forceinline__ uint32_t smem_u32(const void* p) {
    uint32_t a;
    asm("{ .reg .u64 t; cvta.to.shared.u64 t, %1; cvt.u32.u64 %0, t; }"
        : "=r"(a) : "l"(p));
    return a;
}
__device__ __forceinline__ void ldsm4(uint32_t& r0, uint32_t& r1,
                                      uint32_t& r2, uint32_t& r3, uint32_t addr)
{
    asm volatile("ldmatrix.sync.aligned.m8n8.x4.shared.b16 {%0,%1,%2,%3}, [%4];"
                 : "=r"(r0), "=r"(r1), "=r"(r2), "=r"(r3) : "r"(addr));
}
__device__ __forceinline__ void mma16816(float* c, const uint32_t* a,
                                         const uint32_t* b)
{
    asm volatile(
        "mma.sync.aligned.m16n8k16.row.col.f32.bf16.bf16.f32 "
        "{%0,%1,%2,%3}, {%4,%5,%6,%7}, {%8,%9}, {%0,%1,%2,%3};"
        : "+f"(c[0]), "+f"(c[1]), "+f"(c[2]), "+f"(c[3])
        : "r"(a[0]), "r"(a[1]), "r"(a[2]), "r"(a[3]), "r"(b[0]), "r"(b[1]));
}

// ---------------------------------------------------------------------------
// Weight split: W[N][K] fp32 -> hi/lo bf16 [N][Kp]
// ---------------------------------------------------------------------------
__global__ void split_mat_kernel(const float* __restrict__ W,
                                 bf16* __restrict__ hi, bf16* __restrict__ lo,
                                 int N, int K, int Kp)
{
    for (int i = blockIdx.x * blockDim.x + threadIdx.x; i < N * K;
         i += gridDim.x * blockDim.x) {
        int r = i / K, c = i - r * K;
        split2(W[i], &hi[(size_t)r * Kp + c], &lo[(size_t)r * Kp + c]);
    }
}

// ---------------------------------------------------------------------------
// Stage 1: embedding gather + masked mean + first-token feature -> split bf16
// Tokens staged via smem; 4-way unrolled gather loop for MLP.
// ---------------------------------------------------------------------------
__global__ void __launch_bounds__(256) embed_mean_kernel(
    const int* __restrict__ x, const float* __restrict__ emb,
    bf16* __restrict__ fhi, bf16* __restrict__ flo)
{
    const int b = blockIdx.x;
    __shared__ int toks[SEQ];
    __shared__ int s_last;
    const int t = threadIdx.x;

    if (t < SEQ) toks[t] = x[t * BATCH + b];
    __syncthreads();
    if (t == 0) {
        int last = SEQ - 1;
        for (int s = SEQ - 1; s >= 0; --s)
            if (toks[s] != PADTOK) { last = s; break; }
        s_last = last;
    }
    __syncthreads();

    const int last = s_last;
    const float inv = 1.0f / (float)(last + 1);
    const bool hi2 = (t + 256 < EDIM);

    float a0 = 0.f, b0 = 0.f, c0 = 0.f, d0 = 0.f;
    float a1 = 0.f, b1 = 0.f, c1 = 0.f, d1 = 0.f;
    int s = 0;
    for (; s + 4 <= last + 1; s += 4) {
        const float* r0 = emb + (size_t)toks[s]     * EDIM;
        const float* r1 = emb + (size_t)toks[s + 1] * EDIM;
        const float* r2 = emb + (size_t)toks[s + 2] * EDIM;
        const float* r3 = emb + (size_t)toks[s + 3] * EDIM;
        a0 += r0[t]; b0 += r1[t]; c0 += r2[t]; d0 += r3[t];
        if (hi2) {
            a1 += r0[t + 256]; b1 += r1[t + 256];
            c1 += r2[t + 256]; d1 += r3[t + 256];
        }
    }
    for (; s <= last; ++s) {
        const float* r0 = emb + (size_t)toks[s] * EDIM;
        a0 += r0[t];
        if (hi2) a1 += r0[t + 256];
    }
    const float acc0 = (a0 + b0) + (c0 + d0);
    const float acc1 = (a1 + b1) + (c1 + d1);

    const float* row0 = emb + (size_t)toks[0] * EDIM;   // s = 0
    bf16* fh = fhi + (size_t)b * K1P;
    bf16* fl = flo + (size_t)b * K1P;
    split2(row0[t],    &fh[t],        &fl[t]);
    split2(acc0 * inv, &fh[EDIM + t], &fl[EDIM + t]);
    if (hi2) {
        split2(row0[t + 256], &fh[t + 256],        &fl[t + 256]);
        split2(acc1 * inv,    &fh[EDIM + t + 256], &fl[EDIM + t + 256]);
    }
}

// ---------------------------------------------------------------------------
// Fused split-bf16 tensor GEMM: C = A@W^T via AhiBhi + AhiBlo + AloBhi,
// all three combos per K-tile into shared accumulators.
// CTA tile 128x128, BK=32, 8 warps (2x4), warp tile 64x32, mma.m16n8k16.
// cp.async 3-stage pipeline; smem rows padded to 40 bf16 (80B) ->
// conflict-free ldmatrix (validated R7 mapping).
// ---------------------------------------------------------------------------
#define BM 128
#define BN 128
#define BK 32
#define LDSH 40
#define TILE_B (BM * LDSH * 2)          // 10240 B per tile
#define STAGE_B (4 * TILE_B)            // Ahi,Alo,Bhi,Blo = 40960 B
#define STAGES 3
#define GEMM_SMEM (STAGES * STAGE_B)    // 122880 B

template<int SPLIT_RELU_OUT>
__global__ void __launch_bounds__(256) gemm_bf16f_kernel(
    const bf16* __restrict__ aHi, const bf16* __restrict__ aLo,
    const bf16* __restrict__ bHi, const bf16* __restrict__ bLo,
    const float* __restrict__ bias,
    float* __restrict__ outF, bf16* __restrict__ outHi, bf16* __restrict__ outLo,
    int N, int K)
{
    extern __shared__ char smem[];
    const uint32_t sbase = smem_u32(smem);

    const int tid  = threadIdx.x;
    const int lane = tid & 31;
    const int warp = tid >> 5;
    const int warpM = (warp >> 2) * 64;
    const int warpN = (warp & 3) * 32;
    const int mBase = blockIdx.y * BM;
    const int nBase = blockIdx.x * BN;
    const int KT = K / BK;

    // fill mapping: thread -> row frow (0..127), two 16B chunks fc, fc+1
    const int frow = tid >> 1;
    const int fc   = (tid & 1) * 2;     // chunk index base (16B units)
    const size_t aoff = (size_t)(mBase + frow) * K;
    const int nrow = nBase + frow;
    const bool bv = nrow < N;
    const size_t boff = (size_t)(bv ? nrow : 0) * K;
    const int bsz = bv ? 16 : 0;
    const uint32_t srow = (uint32_t)(frow * (LDSH * 2));   // smem row byte offset

    float acc[4][4][4];
    #pragma unroll
    for (int mi = 0; mi < 4; ++mi)
        #pragma unroll
        for (int ni = 0; ni < 4; ++ni)
            #pragma unroll
            for (int q = 0; q < 4; ++q) acc[mi][ni][q] = 0.0f;

    // fill stage (ts = k-tile index); commit even when empty to keep groups aligned
    auto fill = [&](int ts) {
        if (ts < KT) {
            const int st = ts % STAGES;
            const uint32_t sb = sbase + st * STAGE_B;
            const int kk = ts * BK;
            #pragma unroll
            for (int j = 0; j < 2; ++j) {
                const int cb = (fc + j) * 16;          // byte offset in 64B row
                const int ce = (fc + j) * 8;           // bf16 elem offset
                cp_async16(sb + 0 * TILE_B + srow + cb, aHi + aoff + kk + ce, 16);
                cp_async16(sb + 1 * TILE_B + srow + cb, aLo + aoff + kk + ce, 16);
                cp_async16(sb + 2 * TILE_B + srow + cb, bHi + boff + kk + ce, bsz);
                cp_async16(sb + 3 * TILE_B + srow + cb, bLo + boff + kk + ce, bsz);
            }
        }
        CP_COMMIT();
    };

    // ldmatrix per-lane address components (bf16 element offsets) — R7 mapping
    const int g  = lane >> 3;
    const int ri = lane & 7;
    const int aOff = (warpM + ((g & 1) << 3) + ri) * LDSH + ((g >> 1) << 3);
    const int bOff = (warpN + ((g >> 1) << 3) + ri) * LDSH + ((g & 1) << 3);

    fill(0);
    fill(1);

    for (int t = 0; t < KT; ++t) {
        CP_WAIT1();
        __syncthreads();
        fill(t + 2);

        const uint32_t sb  = sbase + (t % STAGES) * STAGE_B;
        const uint32_t sAh = sb;
        const uint32_t sAl = sb + TILE_B;
        const uint32_t sBh = sb + 2 * TILE_B;
        const uint32_t sBl = sb + 3 * TILE_B;

        #pragma unroll
        for (int kh = 0; kh < 2; ++kh) {
            const int kc = kh * 16;
            // B fragments (hi and lo)
            uint32_t bh[4][2], bl[4][2];
            #pragma unroll
            for (int nj = 0; nj < 2; ++nj) {
                uint32_t r0, r1, r2, r3;
                ldsm4(r0, r1, r2, r3,
                      sBh + (uint32_t)(bOff + nj * 16 * LDSH + kc) * 2u);
                bh[2 * nj][0] = r0; bh[2 * nj][1] = r1;
                bh[2 * nj + 1][0] = r2; bh[2 * nj + 1][1] = r3;
                ldsm4(r0, r1, r2, r3,
                      sBl + (uint32_t)(bOff + nj * 16 * LDSH + kc) * 2u);
                bl[2 * nj][0] = r0; bl[2 * nj][1] = r1;
                bl[2 * nj + 1][0] = r2; bl[2 * nj + 1][1] = r3;
            }
            // A hi fragments: mma with Bhi and Blo
            #pragma unroll
            for (int mi = 0; mi < 4; ++mi) {
                uint32_t af[4];
                ldsm4(af[0], af[1], af[2], af[3],
                      sAh + (uint32_t)(aOff + mi * 16 * LDSH + kc) * 2u);
                #pragma unroll
                for (int ni = 0; ni < 4; ++ni) {
                    mma16816(acc[mi][ni], af, bh[ni]);
                    mma16816(acc[mi][ni], af, bl[ni]);
                }
            }
            // A lo fragments: mma with Bhi only
            #pragma unroll
            for (int mi = 0; mi < 4; ++mi) {
                uint32_t af[4];
                ldsm4(af[0], af[1], af[2], af[3],
                      sAl + (uint32_t)(aOff + mi * 16 * LDSH + kc) * 2u);
                #pragma unroll
                for (int ni = 0; ni < 4; ++ni)
                    mma16816(acc[mi][ni], af, bh[ni]);
            }
        }
        __syncthreads();
    }
    CP_WAIT0();

    // epilogue: c-fragment m16n8: (rr,cc),(rr,cc+1),(rr+8,cc),(rr+8,cc+1)
    const int rr = lane >> 2;
    const int cc = (lane & 3) * 2;
    #pragma unroll
    for (int mi = 0; mi < 4; ++mi) {
        #pragma unroll
        for (int ni = 0; ni < 4; ++ni) {
            const int r0g = mBase + warpM + mi * 16 + rr;
            const int c0g = nBase + warpN + ni * 8 + cc;
            const float* a = acc[mi][ni];
            #pragma unroll
            for (int q = 0; q < 4; ++q) {
                const int r = r0g + (q >> 1) * 8;
                const int c = c0g + (q & 1);
                if (SPLIT_RELU_OUT) {
                    float v = fmaxf(a[q] + bias[c], 0.0f);
                    split2(v, &outHi[(size_t)r * N + c], &outLo[(size_t)r * N + c]);
                } else {
                    if (c < N)
                        outF[(size_t)r * N + c] = a[q] + bias[c];
                }
            }
        }
    }
}

// ---------------------------------------------------------------------------
extern "C" void kernel_launch(void* const* d_in, const int* in_sizes, int n_in,
                              void* d_out, int out_size)
{
    const int*   x     = (const int*)  d_in[0];
    const float* emb   = (const float*)d_in[1];
    const float* W1    = (const float*)d_in[2];
    const float* b1    = (const float*)d_in[3];
    const float* W2    = (const float*)d_in[4];
    const float* b2    = (const float*)d_in[5];
    const float* W_out = (const float*)d_in[6];
    const float* b_out = (const float*)d_in[7];
    float* out = (float*)d_out;

    bf16 *fhi, *flo, *h1hi, *h1lo, *h2hi, *h2lo;
    bf16 *w1hi, *w1lo, *w2hi, *w2lo, *wohi, *wolo;
    cudaGetSymbolAddress((void**)&fhi,  g_feat_hi);
    cudaGetSymbolAddress((void**)&flo,  g_feat_lo);
    cudaGetSymbolAddress((void**)&h1hi, g_h1_hi);
    cudaGetSymbolAddress((void**)&h1lo, g_h1_lo);
    cudaGetSymbolAddress((void**)&h2hi, g_h2_hi);
    cudaGetSymbolAddress((void**)&h2lo, g_h2_lo);
    cudaGetSymbolAddress((void**)&w1hi, g_W1_hi);
    cudaGetSymbolAddress((void**)&w1lo, g_W1_lo);
    cudaGetSymbolAddress((void**)&w2hi, g_W2_hi);
    cudaGetSymbolAddress((void**)&w2lo, g_W2_lo);
    cudaGetSymbolAddress((void**)&wohi, g_Wo_hi);
    cudaGetSymbolAddress((void**)&wolo, g_Wo_lo);

    cudaFuncSetAttribute(gemm_bf16f_kernel<1>,
                         cudaFuncAttributeMaxDynamicSharedMemorySize, GEMM_SMEM);
    cudaFuncSetAttribute(gemm_bf16f_kernel<0>,
                         cudaFuncAttributeMaxDynamicSharedMemorySize, GEMM_SMEM);

    split_mat_kernel<<<1024, 256>>>(W1,    w1hi, w1lo, H1D,  K1,  K1P);
    split_mat_kernel<<<1024, 256>>>(W2,    w2hi, w2lo, H2D,  H1D, H1D);
    split_mat_kernel<<<1024, 256>>>(W_out, wohi, wolo, CDIM, H2D, H2D);

    embed_mean_kernel<<<BATCH, 256>>>(x, emb, fhi, flo);

    // Stage 2: h1 = relu(feat @ W1^T + b1)  [8192 x 2048], K=640
    {
        dim3 grid(H1D / BN, BATCH / BM);
        gemm_bf16f_kernel<1><<<grid, 256, GEMM_SMEM>>>(fhi, flo, w1hi, w1lo, b1,
                                                       nullptr, h1hi, h1lo, H1D, K1P);
    }
    // Stage 3: h2 = relu(h1 @ W2^T + b2)    [8192 x 2048], K=2048
    {
        dim3 grid(H2D / BN, BATCH / BM);
        gemm_bf16f_kernel<1><<<grid, 256, GEMM_SMEM>>>(h1hi, h1lo, w2hi, w2lo, b2,
                                                       nullptr, h2hi, h2lo, H2D, H1D);
    }
    // Stage 4: out = h2 @ W_out^T + b_out   [8192 x 1221], K=2048, fp32 out
    {
        dim3 grid((CDIM + BN - 1) / BN, BATCH / BM);
        gemm_bf16f_kernel<0><<<grid, 256, GEMM_SMEM>>>(h2hi, h2lo, wohi, wolo, b_out,
                                                       out, nullptr, nullptr, CDIM, H2D);
    }
}

// round 15
// speedup vs baseline: 1.7124x; 1.7124x over previous
#include <cuda_runtime.h>
#include <cuda_bf16.h>
#include <cstdint>

// Problem dims
#define BATCH 8192
#define SEQ   128
#define EDIM  300
#define K1    600
#define K1P   640     // padded to multiple of BK
#define H1D   2048
#define H2D   2048
#define CDIM  1221
#define PADTOK 1

typedef __nv_bfloat16 bf16;

// ---------------------------------------------------------------------------
// Scratch (__device__ globals; zero-init -> K-padding cols stay zero)
// ---------------------------------------------------------------------------
__device__ bf16 g_feat_hi[(size_t)BATCH * K1P];
__device__ bf16 g_feat_lo[(size_t)BATCH * K1P];
__device__ bf16 g_h1_hi[(size_t)BATCH * H1D];
__device__ bf16 g_h1_lo[(size_t)BATCH * H1D];
__device__ bf16 g_h2_hi[(size_t)BATCH * H2D];
__device__ bf16 g_h2_lo[(size_t)BATCH * H2D];
__device__ bf16 g_W1_hi[(size_t)H1D * K1P];
__device__ bf16 g_W1_lo[(size_t)H1D * K1P];
__device__ bf16 g_W2_hi[(size_t)H2D * H1D];
__device__ bf16 g_W2_lo[(size_t)H2D * H1D];
__device__ bf16 g_Wo_hi[(size_t)CDIM * H2D];
__device__ bf16 g_Wo_lo[(size_t)CDIM * H2D];

__device__ __forceinline__ void split2(float v, bf16* hi, bf16* lo) {
    bf16 h = __float2bfloat16(v);
    *hi = h;
    *lo = __float2bfloat16(v - __bfloat162float(h));
}

// ---------------------------------------------------------------------------
// cp.async helpers (Ampere+; valid on base sm_103 target)
// ---------------------------------------------------------------------------
__device__ __forceinline__ void cp_async16(uint32_t dst, const void* src, int sz) {
    asm volatile("cp.async.cg.shared.global [%0], [%1], 16, %2;"
                 :: "r"(dst), "l"(src), "r"(sz) : "memory");
}
#define CP_COMMIT() asm volatile("cp.async.commit_group;" ::: "memory")
#define CP_WAIT1()  asm volatile("cp.async.wait_group 1;" ::: "memory")
#define CP_WAIT0()  asm volatile("cp.async.wait_group 0;" ::: "memory")

__device__ __forceinline__ uint32_t smem_u32(const void* p) {
    uint32_t a;
    asm("{ .reg .u64 t; cvta.to.shared.u64 t, %1; cvt.u32.u64 %0, t; }"
        : "=r"(a) : "l"(p));
    return a;
}
__device__ __forceinline__ void ldsm4(uint32_t& r0, uint32_t& r1,
                                      uint32_t& r2, uint32_t& r3, uint32_t addr)
{
    asm volatile("ldmatrix.sync.aligned.m8n8.x4.shared.b16 {%0,%1,%2,%3}, [%4];"
                 : "=r"(r0), "=r"(r1), "=r"(r2), "=r"(r3) : "r"(addr));
}
__device__ __forceinline__ void mma16816(float* c, const uint32_t* a,
                                         const uint32_t* b)
{
    asm volatile(
        "mma.sync.aligned.m16n8k16.row.col.f32.bf16.bf16.f32 "
        "{%0,%1,%2,%3}, {%4,%5,%6,%7}, {%8,%9}, {%0,%1,%2,%3};"
        : "+f"(c[0]), "+f"(c[1]), "+f"(c[2]), "+f"(c[3])
        : "r"(a[0]), "r"(a[1]), "r"(a[2]), "r"(a[3]), "r"(b[0]), "r"(b[1]));
}

// ---------------------------------------------------------------------------
// Weight split: W[N][K] fp32 -> hi/lo bf16 [N][Kp]
// ---------------------------------------------------------------------------
__global__ void split_mat_kernel(const float* __restrict__ W,
                                 bf16* __restrict__ hi, bf16* __restrict__ lo,
                                 int N, int K, int Kp)
{
    for (int i = blockIdx.x * blockDim.x + threadIdx.x; i < N * K;
         i += gridDim.x * blockDim.x) {
        int r = i / K, c = i - r * K;
        split2(W[i], &hi[(size_t)r * Kp + c], &lo[(size_t)r * Kp + c]);
    }
}

// ---------------------------------------------------------------------------
// Stage 1: embedding gather + masked mean + first-token feature -> split bf16
// Tokens staged via smem; 4-way unrolled gather loop for MLP.
// ---------------------------------------------------------------------------
__global__ void __launch_bounds__(256) embed_mean_kernel(
    const int* __restrict__ x, const float* __restrict__ emb,
    bf16* __restrict__ fhi, bf16* __restrict__ flo)
{
    const int b = blockIdx.x;
    __shared__ int toks[SEQ];
    __shared__ int s_last;
    const int t = threadIdx.x;

    if (t < SEQ) toks[t] = x[t * BATCH + b];
    __syncthreads();
    if (t == 0) {
        int last = SEQ - 1;
        for (int s = SEQ - 1; s >= 0; --s)
            if (toks[s] != PADTOK) { last = s; break; }
        s_last = last;
    }
    __syncthreads();

    const int last = s_last;
    const float inv = 1.0f / (float)(last + 1);
    const bool hi2 = (t + 256 < EDIM);

    float a0 = 0.f, b0 = 0.f, c0 = 0.f, d0 = 0.f;
    float a1 = 0.f, b1 = 0.f, c1 = 0.f, d1 = 0.f;
    int s = 0;
    for (; s + 4 <= last + 1; s += 4) {
        const float* r0 = emb + (size_t)toks[s]     * EDIM;
        const float* r1 = emb + (size_t)toks[s + 1] * EDIM;
        const float* r2 = emb + (size_t)toks[s + 2] * EDIM;
        const float* r3 = emb + (size_t)toks[s + 3] * EDIM;
        a0 += r0[t]; b0 += r1[t]; c0 += r2[t]; d0 += r3[t];
        if (hi2) {
            a1 += r0[t + 256]; b1 += r1[t + 256];
            c1 += r2[t + 256]; d1 += r3[t + 256];
        }
    }
    for (; s <= last; ++s) {
        const float* r0 = emb + (size_t)toks[s] * EDIM;
        a0 += r0[t];
        if (hi2) a1 += r0[t + 256];
    }
    const float acc0 = (a0 + b0) + (c0 + d0);
    const float acc1 = (a1 + b1) + (c1 + d1);

    const float* row0 = emb + (size_t)toks[0] * EDIM;   // s = 0
    bf16* fh = fhi + (size_t)b * K1P;
    bf16* fl = flo + (size_t)b * K1P;
    split2(row0[t],    &fh[t],        &fl[t]);
    split2(acc0 * inv, &fh[EDIM + t], &fl[EDIM + t]);
    if (hi2) {
        split2(row0[t + 256], &fh[t + 256],        &fl[t + 256]);
        split2(acc1 * inv,    &fh[EDIM + t + 256], &fl[EDIM + t + 256]);
    }
}

// ---------------------------------------------------------------------------
// Fused split-bf16 tensor GEMM: C = A@W^T via AhiBhi + AhiBlo + AloBhi,
// all three combos per K-tile into shared accumulators.
// CTA tile 128x128, BK=32, 8 warps (2x4), warp tile 64x32, mma.m16n8k16.
// 2-stage cp.async pipeline (81920 B smem -> 2 CTAs/SM, 16 warps/SM for
// ldsm/mma latency hiding); smem rows padded to 40 bf16 (80B) ->
// conflict-free ldmatrix (validated R7 mapping).
// ---------------------------------------------------------------------------
#define BM 128
#define BN 128
#define BK 32
#define LDSH 40
#define TILE_B (BM * LDSH * 2)          // 10240 B per tile
#define STAGE_B (4 * TILE_B)            // Ahi,Alo,Bhi,Blo = 40960 B
#define STAGES 2
#define GEMM_SMEM (STAGES * STAGE_B)    // 81920 B

template<int SPLIT_RELU_OUT>
__global__ void __launch_bounds__(256, 2) gemm_bf16f_kernel(
    const bf16* __restrict__ aHi, const bf16* __restrict__ aLo,
    const bf16* __restrict__ bHi, const bf16* __restrict__ bLo,
    const float* __restrict__ bias,
    float* __restrict__ outF, bf16* __restrict__ outHi, bf16* __restrict__ outLo,
    int N, int K)
{
    extern __shared__ char smem[];
    const uint32_t sbase = smem_u32(smem);

    const int tid  = threadIdx.x;
    const int lane = tid & 31;
    const int warp = tid >> 5;
    const int warpM = (warp >> 2) * 64;
    const int warpN = (warp & 3) * 32;
    const int mBase = blockIdx.y * BM;
    const int nBase = blockIdx.x * BN;
    const int KT = K / BK;

    // fill mapping: thread -> row frow (0..127), two 16B chunks fc, fc+1
    const int frow = tid >> 1;
    const int fc   = (tid & 1) * 2;     // chunk index base (16B units)
    const size_t aoff = (size_t)(mBase + frow) * K;
    const int nrow = nBase + frow;
    const bool bv = nrow < N;
    const size_t boff = (size_t)(bv ? nrow : 0) * K;
    const int bsz = bv ? 16 : 0;
    const uint32_t srow = (uint32_t)(frow * (LDSH * 2));   // smem row byte offset

    float acc[4][4][4];
    #pragma unroll
    for (int mi = 0; mi < 4; ++mi)
        #pragma unroll
        for (int ni = 0; ni < 4; ++ni)
            #pragma unroll
            for (int q = 0; q < 4; ++q) acc[mi][ni][q] = 0.0f;

    // fill stage (ts = k-tile index); commit even when empty to keep groups aligned
    auto fill = [&](int ts) {
        if (ts < KT) {
            const int st = ts & 1;
            const uint32_t sb = sbase + st * STAGE_B;
            const int kk = ts * BK;
            #pragma unroll
            for (int j = 0; j < 2; ++j) {
                const int cb = (fc + j) * 16;          // byte offset in 64B row
                const int ce = (fc + j) * 8;           // bf16 elem offset
                cp_async16(sb + 0 * TILE_B + srow + cb, aHi + aoff + kk + ce, 16);
                cp_async16(sb + 1 * TILE_B + srow + cb, aLo + aoff + kk + ce, 16);
                cp_async16(sb + 2 * TILE_B + srow + cb, bHi + boff + kk + ce, bsz);
                cp_async16(sb + 3 * TILE_B + srow + cb, bLo + boff + kk + ce, bsz);
            }
        }
        CP_COMMIT();
    };

    // ldmatrix per-lane address components (bf16 element offsets) — R7 mapping
    const int g  = lane >> 3;
    const int ri = lane & 7;
    const int aOff = (warpM + ((g & 1) << 3) + ri) * LDSH + ((g >> 1) << 3);
    const int bOff = (warpN + ((g >> 1) << 3) + ri) * LDSH + ((g & 1) << 3);

    fill(0);
    fill(1);

    for (int t = 0; t < KT; ++t) {
        CP_WAIT1();
        __syncthreads();

        const uint32_t sb  = sbase + (t & 1) * STAGE_B;
        const uint32_t sAh = sb;
        const uint32_t sAl = sb + TILE_B;
        const uint32_t sBh = sb + 2 * TILE_B;
        const uint32_t sBl = sb + 3 * TILE_B;

        #pragma unroll
        for (int kh = 0; kh < 2; ++kh) {
            const int kc = kh * 16;
            // B fragments (hi and lo)
            uint32_t bh[4][2], bl[4][2];
            #pragma unroll
            for (int nj = 0; nj < 2; ++nj) {
                uint32_t r0, r1, r2, r3;
                ldsm4(r0, r1, r2, r3,
                      sBh + (uint32_t)(bOff + nj * 16 * LDSH + kc) * 2u);
                bh[2 * nj][0] = r0; bh[2 * nj][1] = r1;
                bh[2 * nj + 1][0] = r2; bh[2 * nj + 1][1] = r3;
                ldsm4(r0, r1, r2, r3,
                      sBl + (uint32_t)(bOff + nj * 16 * LDSH + kc) * 2u);
                bl[2 * nj][0] = r0; bl[2 * nj][1] = r1;
                bl[2 * nj + 1][0] = r2; bl[2 * nj + 1][1] = r3;
            }
            // A hi fragments: mma with Bhi and Blo
            #pragma unroll
            for (int mi = 0; mi < 4; ++mi) {
                uint32_t af[4];
                ldsm4(af[0], af[1], af[2], af[3],
                      sAh + (uint32_t)(aOff + mi * 16 * LDSH + kc) * 2u);
                #pragma unroll
                for (int ni = 0; ni < 4; ++ni) {
                    mma16816(acc[mi][ni], af, bh[ni]);
                    mma16816(acc[mi][ni], af, bl[ni]);
                }
            }
            // A lo fragments: mma with Bhi only
            #pragma unroll
            for (int mi = 0; mi < 4; ++mi) {
                uint32_t af[4];
                ldsm4(af[0], af[1], af[2], af[3],
                      sAl + (uint32_t)(aOff + mi * 16 * LDSH + kc) * 2u);
                #pragma unroll
                for (int ni = 0; ni < 4; ++ni)
                    mma16816(acc[mi][ni], af, bh[ni]);
            }
        }

        __syncthreads();       // compute done before refilling this buffer
        fill(t + 2);
    }
    CP_WAIT0();

    // epilogue: c-fragment m16n8: (rr,cc),(rr,cc+1),(rr+8,cc),(rr+8,cc+1)
    const int rr = lane >> 2;
    const int cc = (lane & 3) * 2;
    #pragma unroll
    for (int mi = 0; mi < 4; ++mi) {
        #pragma unroll
        for (int ni = 0; ni < 4; ++ni) {
            const int r0g = mBase + warpM + mi * 16 + rr;
            const int c0g = nBase + warpN + ni * 8 + cc;
            const float* a = acc[mi][ni];
            #pragma unroll
            for (int q = 0; q < 4; ++q) {
                const int r = r0g + (q >> 1) * 8;
                const int c = c0g + (q & 1);
                if (SPLIT_RELU_OUT) {
                    float v = fmaxf(a[q] + bias[c], 0.0f);
                    split2(v, &outHi[(size_t)r * N + c], &outLo[(size_t)r * N + c]);
                } else {
                    if (c < N)
                        outF[(size_t)r * N + c] = a[q] + bias[c];
                }
            }
        }
    }
}

// ---------------------------------------------------------------------------
extern "C" void kernel_launch(void* const* d_in, const int* in_sizes, int n_in,
                              void* d_out, int out_size)
{
    const int*   x     = (const int*)  d_in[0];
    const float* emb   = (const float*)d_in[1];
    const float* W1    = (const float*)d_in[2];
    const float* b1    = (const float*)d_in[3];
    const float* W2    = (const float*)d_in[4];
    const float* b2    = (const float*)d_in[5];
    const float* W_out = (const float*)d_in[6];
    const float* b_out = (const float*)d_in[7];
    float* out = (float*)d_out;

    bf16 *fhi, *flo, *h1hi, *h1lo, *h2hi, *h2lo;
    bf16 *w1hi, *w1lo, *w2hi, *w2lo, *wohi, *wolo;
    cudaGetSymbolAddress((void**)&fhi,  g_feat_hi);
    cudaGetSymbolAddress((void**)&flo,  g_feat_lo);
    cudaGetSymbolAddress((void**)&h1hi, g_h1_hi);
    cudaGetSymbolAddress((void**)&h1lo, g_h1_lo);
    cudaGetSymbolAddress((void**)&h2hi, g_h2_hi);
    cudaGetSymbolAddress((void**)&h2lo, g_h2_lo);
    cudaGetSymbolAddress((void**)&w1hi, g_W1_hi);
    cudaGetSymbolAddress((void**)&w1lo, g_W1_lo);
    cudaGetSymbolAddress((void**)&w2hi, g_W2_hi);
    cudaGetSymbolAddress((void**)&w2lo, g_W2_lo);
    cudaGetSymbolAddress((void**)&wohi, g_Wo_hi);
    cudaGetSymbolAddress((void**)&wolo, g_Wo_lo);

    cudaFuncSetAttribute(gemm_bf16f_kernel<1>,
                         cudaFuncAttributeMaxDynamicSharedMemorySize, GEMM_SMEM);
    cudaFuncSetAttribute(gemm_bf16f_kernel<0>,
                         cudaFuncAttributeMaxDynamicSharedMemorySize, GEMM_SMEM);

    split_mat_kernel<<<1024, 256>>>(W1,    w1hi, w1lo, H1D,  K1,  K1P);
    split_mat_kernel<<<1024, 256>>>(W2,    w2hi, w2lo, H2D,  H1D, H1D);
    split_mat_kernel<<<1024, 256>>>(W_out, wohi, wolo, CDIM, H2D, H2D);

    embed_mean_kernel<<<BATCH, 256>>>(x, emb, fhi, flo);

    // Stage 2: h1 = relu(feat @ W1^T + b1)  [8192 x 2048], K=640
    {
        dim3 grid(H1D / BN, BATCH / BM);
        gemm_bf16f_kernel<1><<<grid, 256, GEMM_SMEM>>>(fhi, flo, w1hi, w1lo, b1,
                                                       nullptr, h1hi, h1lo, H1D, K1P);
    }
    // Stage 3: h2 = relu(h1 @ W2^T + b2)    [8192 x 2048], K=2048
    {
        dim3 grid(H2D / BN, BATCH / BM);
        gemm_bf16f_kernel<1><<<grid, 256, GEMM_SMEM>>>(h1hi, h1lo, w2hi, w2lo, b2,
                                                       nullptr, h2hi, h2lo, H2D, H1D);
    }
    // Stage 4: out = h2 @ W_out^T + b_out   [8192 x 1221], K=2048, fp32 out
    {
        dim3 grid((CDIM + BN - 1) / BN, BATCH / BM);
        gemm_bf16f_kernel<0><<<grid, 256, GEMM_SMEM>>>(h2hi, h2lo, wohi, wolo, b_out,
                                                       out, nullptr, nullptr, CDIM, H2D);
    }
}

// round 17
// speedup vs baseline: 3.7017x; 2.1617x over previous
#include <cuda_runtime.h>
#include <cuda_fp16.h>
#include <cstdint>

// Problem dims
#define BATCH 8192
#define SEQ   128
#define EDIM  300
#define K1    600
#define K1P   608     // padded to multiple of BK (19*32)
#define H1D   2048
#define H2D   2048
#define CDIM  1221
#define PADTOK 1

typedef __half fp16;

// ---------------------------------------------------------------------------
// Scratch (__device__ globals; zero-init -> K-padding cols stay zero)
// ---------------------------------------------------------------------------
__device__ fp16 g_feat[(size_t)BATCH * K1P];
__device__ fp16 g_h1[(size_t)BATCH * H1D];
__device__ fp16 g_h2[(size_t)BATCH * H2D];
__device__ fp16 g_W1[(size_t)H1D * K1P];
__device__ fp16 g_W2[(size_t)H2D * H1D];
__device__ fp16 g_Wo[(size_t)CDIM * H2D];

// ---------------------------------------------------------------------------
// cp.async helpers (Ampere+; valid on base sm_103 target)
// ---------------------------------------------------------------------------
__device__ __forceinline__ void cp_async16(uint32_t dst, const void* src, int sz) {
    asm volatile("cp.async.cg.shared.global [%0], [%1], 16, %2;"
                 :: "r"(dst), "l"(src), "r"(sz) : "memory");
}
#define CP_COMMIT() asm volatile("cp.async.commit_group;" ::: "memory")
#define CP_WAIT2()  asm volatile("cp.async.wait_group 2;" ::: "memory")
#define CP_WAIT0()  asm volatile("cp.async.wait_group 0;" ::: "memory")

__device__ __forceinline__ uint32_t smem_u32(const void* p) {
    uint32_t a;
    asm("{ .reg .u64 t; cvta.to.shared.u64 t, %1; cvt.u32.u64 %0, t; }"
        : "=r"(a) : "l"(p));
    return a;
}
__device__ __forceinline__ void ldsm4(uint32_t& r0, uint32_t& r1,
                                      uint32_t& r2, uint32_t& r3, uint32_t addr)
{
    asm volatile("ldmatrix.sync.aligned.m8n8.x4.shared.b16 {%0,%1,%2,%3}, [%4];"
                 : "=r"(r0), "=r"(r1), "=r"(r2), "=r"(r3) : "r"(addr));
}
__device__ __forceinline__ void mma16816(float* c, const uint32_t* a,
                                         const uint32_t* b)
{
    asm volatile(
        "mma.sync.aligned.m16n8k16.row.col.f32.f16.f16.f32 "
        "{%0,%1,%2,%3}, {%4,%5,%6,%7}, {%8,%9}, {%0,%1,%2,%3};"
        : "+f"(c[0]), "+f"(c[1]), "+f"(c[2]), "+f"(c[3])
        : "r"(a[0]), "r"(a[1]), "r"(a[2]), "r"(a[3]), "r"(b[0]), "r"(b[1]));
}

// ---------------------------------------------------------------------------
// Weight convert: W[N][K] fp32 -> fp16 [N][Kp]
// ---------------------------------------------------------------------------
__global__ void conv_mat_kernel(const float* __restrict__ W,
                                fp16* __restrict__ out, int N, int K, int Kp)
{
    for (int i = blockIdx.x * blockDim.x + threadIdx.x; i < N * K;
         i += gridDim.x * blockDim.x) {
        int r = i / K, c = i - r * K;
        out[(size_t)r * Kp + c] = __float2half(W[i]);
    }
}

// ---------------------------------------------------------------------------
// Stage 1: embedding gather + masked mean + first-token feature -> fp16
// Tokens staged via smem; 4-way unrolled gather loop for MLP.
// ---------------------------------------------------------------------------
__global__ void __launch_bounds__(256) embed_mean_kernel(
    const int* __restrict__ x, const float* __restrict__ emb,
    fp16* __restrict__ feat)
{
    const int b = blockIdx.x;
    __shared__ int toks[SEQ];
    __shared__ int s_last;
    const int t = threadIdx.x;

    if (t < SEQ) toks[t] = x[t * BATCH + b];
    __syncthreads();
    if (t == 0) {
        int last = SEQ - 1;
        for (int s = SEQ - 1; s >= 0; --s)
            if (toks[s] != PADTOK) { last = s; break; }
        s_last = last;
    }
    __syncthreads();

    const int last = s_last;
    const float inv = 1.0f / (float)(last + 1);
    const bool hi2 = (t + 256 < EDIM);

    float a0 = 0.f, b0 = 0.f, c0 = 0.f, d0 = 0.f;
    float a1 = 0.f, b1 = 0.f, c1 = 0.f, d1 = 0.f;
    int s = 0;
    for (; s + 4 <= last + 1; s += 4) {
        const float* r0 = emb + (size_t)toks[s]     * EDIM;
        const float* r1 = emb + (size_t)toks[s + 1] * EDIM;
        const float* r2 = emb + (size_t)toks[s + 2] * EDIM;
        const float* r3 = emb + (size_t)toks[s + 3] * EDIM;
        a0 += r0[t]; b0 += r1[t]; c0 += r2[t]; d0 += r3[t];
        if (hi2) {
            a1 += r0[t + 256]; b1 += r1[t + 256];
            c1 += r2[t + 256]; d1 += r3[t + 256];
        }
    }
    for (; s <= last; ++s) {
        const float* r0 = emb + (size_t)toks[s] * EDIM;
        a0 += r0[t];
        if (hi2) a1 += r0[t + 256];
    }
    const float acc0 = (a0 + b0) + (c0 + d0);
    const float acc1 = (a1 + b1) + (c1 + d1);

    const float* row0 = emb + (size_t)toks[0] * EDIM;   // s = 0
    fp16* fb = feat + (size_t)b * K1P;
    fb[t]        = __float2half(row0[t]);
    fb[EDIM + t] = __float2half(acc0 * inv);
    if (hi2) {
        fb[t + 256]        = __float2half(row0[t + 256]);
        fb[EDIM + t + 256] = __float2half(acc1 * inv);
    }
}

// ---------------------------------------------------------------------------
// Single-pass fp16 tensor GEMM: C[M,N] = A[M,K] @ W[N,K]^T (+bias, relu)
// CTA tile 128x128, BK=32, 8 warps (2x4), warp tile 64x32, mma.m16n8k16.
// 3-stage cp.async pipeline (61440 B smem -> 2 CTAs/SM); smem rows padded
// to 40 halves (80B) -> conflict-free ldmatrix (validated mapping).
// fp32 output path uses SCALAR stores only: N may be odd (CDIM=1221), so
// any vector store at r*N + c is misaligned for odd r.
// ---------------------------------------------------------------------------
#define BM 128
#define BN 128
#define BK 32
#define LDSH 40
#define TILE_B (BM * LDSH * 2)          // 10240 B per tile
#define STAGE_B (2 * TILE_B)            // A, B = 20480 B
#define STAGES 3
#define GEMM_SMEM (STAGES * STAGE_B)    // 61440 B

template<int RELU_H16_OUT>
__global__ void __launch_bounds__(256, 2) gemm_f16_kernel(
    const fp16* __restrict__ A, const fp16* __restrict__ B,
    const float* __restrict__ bias,
    float* __restrict__ outF, fp16* __restrict__ outH,
    int N, int K)
{
    extern __shared__ char smem[];
    const uint32_t sbase = smem_u32(smem);

    const int tid  = threadIdx.x;
    const int lane = tid & 31;
    const int warp = tid >> 5;
    const int warpM = (warp >> 2) * 64;
    const int warpN = (warp & 3) * 32;
    const int mBase = blockIdx.y * BM;
    const int nBase = blockIdx.x * BN;
    const int KT = K / BK;

    // fill mapping: thread -> row frow (0..127), two 16B chunks fc, fc+1
    const int frow = tid >> 1;
    const int fc   = (tid & 1) * 2;     // chunk index base (16B units)
    const size_t aoff = (size_t)(mBase + frow) * K;
    const int nrow = nBase + frow;
    const bool bv = nrow < N;
    const size_t boff = (size_t)(bv ? nrow : 0) * K;
    const int bsz = bv ? 16 : 0;
    const uint32_t srow = (uint32_t)(frow * (LDSH * 2));   // smem row byte offset

    float acc[4][4][4];
    #pragma unroll
    for (int mi = 0; mi < 4; ++mi)
        #pragma unroll
        for (int ni = 0; ni < 4; ++ni)
            #pragma unroll
            for (int q = 0; q < 4; ++q) acc[mi][ni][q] = 0.0f;

    // fill stage (ts = k-tile index); commit even when empty to keep groups aligned
    auto fill = [&](int ts) {
        if (ts < KT) {
            const int st = ts % STAGES;
            const uint32_t sb = sbase + st * STAGE_B;
            const int kk = ts * BK;
            #pragma unroll
            for (int j = 0; j < 2; ++j) {
                const int cb = (fc + j) * 16;          // byte offset in 64B row
                const int ce = (fc + j) * 8;           // fp16 elem offset
                cp_async16(sb + srow + cb,          A + aoff + kk + ce, 16);
                cp_async16(sb + TILE_B + srow + cb, B + boff + kk + ce, bsz);
            }
        }
        CP_COMMIT();
    };

    // ldmatrix per-lane address components (fp16 element offsets)
    const int g  = lane >> 3;
    const int ri = lane & 7;
    const int aOff = (warpM + ((g & 1) << 3) + ri) * LDSH + ((g >> 1) << 3);
    const int bOff = (warpN + ((g >> 1) << 3) + ri) * LDSH + ((g & 1) << 3);

    fill(0);
    fill(1);
    fill(2);

    for (int t = 0; t < KT; ++t) {
        CP_WAIT2();          // fill(t) complete (<=2 groups pending)
        __syncthreads();

        const uint32_t sb = sbase + (t % STAGES) * STAGE_B;
        const uint32_t sA = sb;
        const uint32_t sB = sb + TILE_B;

        #pragma unroll
        for (int kh = 0; kh < 2; ++kh) {
            const int kc = kh * 16;
            uint32_t bf[4][2];
            #pragma unroll
            for (int nj = 0; nj < 2; ++nj) {
                uint32_t r0, r1, r2, r3;
                ldsm4(r0, r1, r2, r3,
                      sB + (uint32_t)(bOff + nj * 16 * LDSH + kc) * 2u);
                bf[2 * nj][0] = r0; bf[2 * nj][1] = r1;
                bf[2 * nj + 1][0] = r2; bf[2 * nj + 1][1] = r3;
            }
            #pragma unroll
            for (int mi = 0; mi < 4; ++mi) {
                uint32_t af[4];
                ldsm4(af[0], af[1], af[2], af[3],
                      sA + (uint32_t)(aOff + mi * 16 * LDSH + kc) * 2u);
                #pragma unroll
                for (int ni = 0; ni < 4; ++ni)
                    mma16816(acc[mi][ni], af, bf[ni]);
            }
        }

        __syncthreads();       // all warps done with stage t before refill
        fill(t + 3);
    }
    CP_WAIT0();

    // epilogue: c-fragment m16n8: (rr,cc),(rr,cc+1),(rr+8,cc),(rr+8,cc+1)
    const int rr = lane >> 2;
    const int cc = (lane & 3) * 2;
    #pragma unroll
    for (int mi = 0; mi < 4; ++mi) {
        #pragma unroll
        for (int ni = 0; ni < 4; ++ni) {
            const int r0g = mBase + warpM + mi * 16 + rr;
            const int c0g = nBase + warpN + ni * 8 + cc;
            const float* a = acc[mi][ni];
            #pragma unroll
            for (int h = 0; h < 2; ++h) {         // row halves (rr, rr+8)
                const int r = r0g + h * 8;
                const float v0 = a[h * 2 + 0] + bias[c0g];
                const float v1 = a[h * 2 + 1] + bias[c0g + 1];
                if (RELU_H16_OUT) {
                    // N even here (2048); c0g even -> 4B-aligned half2 store
                    __half2 p = __floats2half2_rn(fmaxf(v0, 0.0f), fmaxf(v1, 0.0f));
                    *(__half2*)(outH + (size_t)r * N + c0g) = p;
                } else {
                    // N may be odd (1221): scalar stores only, per-col guard
                    if (c0g < N)     outF[(size_t)r * N + c0g]     = v0;
                    if (c0g + 1 < N) outF[(size_t)r * N + c0g + 1] = v1;
                }
            }
        }
    }
}

// ---------------------------------------------------------------------------
extern "C" void kernel_launch(void* const* d_in, const int* in_sizes, int n_in,
                              void* d_out, int out_size)
{
    const int*   x     = (const int*)  d_in[0];
    const float* emb   = (const float*)d_in[1];
    const float* W1    = (const float*)d_in[2];
    const float* b1    = (const float*)d_in[3];
    const float* W2    = (const float*)d_in[4];
    const float* b2    = (const float*)d_in[5];
    const float* W_out = (const float*)d_in[6];
    const float* b_out = (const float*)d_in[7];
    float* out = (float*)d_out;

    fp16 *feat, *h1, *h2, *w1, *w2, *wo;
    cudaGetSymbolAddress((void**)&feat, g_feat);
    cudaGetSymbolAddress((void**)&h1,   g_h1);
    cudaGetSymbolAddress((void**)&h2,   g_h2);
    cudaGetSymbolAddress((void**)&w1,   g_W1);
    cudaGetSymbolAddress((void**)&w2,   g_W2);
    cudaGetSymbolAddress((void**)&wo,   g_Wo);

    cudaFuncSetAttribute(gemm_f16_kernel<1>,
                         cudaFuncAttributeMaxDynamicSharedMemorySize, GEMM_SMEM);
    cudaFuncSetAttribute(gemm_f16_kernel<0>,
                         cudaFuncAttributeMaxDynamicSharedMemorySize, GEMM_SMEM);

    conv_mat_kernel<<<1024, 256>>>(W1,    w1, H1D,  K1,  K1P);
    conv_mat_kernel<<<1024, 256>>>(W2,    w2, H2D,  H1D, H1D);
    conv_mat_kernel<<<1024, 256>>>(W_out, wo, CDIM, H2D, H2D);

    embed_mean_kernel<<<BATCH, 256>>>(x, emb, feat);

    // Stage 2: h1 = relu(feat @ W1^T + b1)  [8192 x 2048], K=608
    {
        dim3 grid(H1D / BN, BATCH / BM);
        gemm_f16_kernel<1><<<grid, 256, GEMM_SMEM>>>(feat, w1, b1,
                                                     nullptr, h1, H1D, K1P);
    }
    // Stage 3: h2 = relu(h1 @ W2^T + b2)    [8192 x 2048], K=2048
    {
        dim3 grid(H2D / BN, BATCH / BM);
        gemm_f16_kernel<1><<<grid, 256, GEMM_SMEM>>>(h1, w2, b2,
                                                     nullptr, h2, H2D, H1D);
    }
    // Stage 4: out = h2 @ W_out^T + b_out   [8192 x 1221], K=2048, fp32 out
    {
        dim3 grid((CDIM + BN - 1) / BN, BATCH / BM);
        gemm_f16_kernel<0><<<grid, 256, GEMM_SMEM>>>(h2, wo, b_out,
                                                     out, nullptr, CDIM, H2D);
    }
}